// round 6
// baseline (speedup 1.0000x reference)
#include <cuda_runtime.h>
#include <cstdint>

#define NUM_JOINT 19
#define ROOT_SCALE 200.0f
#define BLOCK 32
#define NTILE 4
#define TILE_FLOATS (BLOCK * NUM_JOINT * 4)   // 2432
#define TILE_BYTES  (TILE_FLOATS * 4)         // 9728

__constant__ float c_off[NUM_JOINT * 16];

__device__ __forceinline__ void mbar_wait(uint32_t mb, uint32_t parity) {
    asm volatile(
        "{\n\t.reg .pred P;\n\t"
        "W%=:\n\t"
        "mbarrier.try_wait.parity.acquire.cta.shared::cta.b64 P, [%0], %1;\n\t"
        "@!P bra W%=;\n\t}"
        :: "r"(mb), "r"(parity) : "memory");
}

__device__ __forceinline__ void tma_load(uint32_t sdst, const float* gsrc, uint32_t mb) {
    asm volatile("mbarrier.arrive.expect_tx.shared.b64 _, [%0], %1;"
                 :: "r"(mb), "r"((uint32_t)TILE_BYTES) : "memory");
    asm volatile("cp.async.bulk.shared::cta.global.mbarrier::complete_tx::bytes "
                 "[%0], [%1], %2, [%3];"
                 :: "r"(sdst), "l"(gsrc), "r"((uint32_t)TILE_BYTES), "r"(mb) : "memory");
}

__global__ __launch_bounds__(BLOCK, 7)
void fk_kernel(const float* __restrict__ root,
               const float* __restrict__ joint,
               float* __restrict__ out)
{
    __shared__ alignas(16) float s[3][TILE_FLOATS];        // 29184 B ring
    __shared__ alignas(8)  unsigned long long mbar[3];

    const int t = threadIdx.x;
    const uint32_t s0 = (uint32_t)__cvta_generic_to_shared(&s[0][0]);
    const uint32_t m0 = (uint32_t)__cvta_generic_to_shared(&mbar[0]);

    if (t == 0) {
        #pragma unroll
        for (int k = 0; k < 3; k++)
            asm volatile("mbarrier.init.shared.b64 [%0], 1;" :: "r"(m0 + k * 8) : "memory");
    }
    __syncwarp();

    const long long tile0 = (long long)blockIdx.x * NTILE;
    const float* gbase = joint + tile0 * TILE_FLOATS;

    // Prologue: prefetch tiles 0 and 1 (depth-2 pipeline head).
    if (t == 0) {
        tma_load(s0,              gbase,               m0);
        tma_load(s0 + TILE_BYTES, gbase + TILE_FLOATS, m0 + 8);
    }

    const int parents[NUM_JOINT] = {-1,0,1,2,3,2,5,6,7,2,9,10,11,0,13,14,0,16,17};

    #pragma unroll
    for (int i = 0; i < NTILE; i++) {
        const int buf    = i % 3;
        const int parity = (i / 3) & 1;

        // Root fetch overlaps the mbar wait window.
        const long long b = (tile0 + i) * BLOCK + t;
        const float rx = __ldg(&root[b * 3 + 0]) * ROOT_SCALE;
        const float ry = __ldg(&root[b * 3 + 1]) * ROOT_SCALE;
        const float rz = __ldg(&root[b * 3 + 2]) * ROOT_SCALE;

        mbar_wait(m0 + buf * 8, (uint32_t)parity);

        // ---- FK chain via composite (non-unit) quaternions, in-place in s[buf] ----
        float gw[NUM_JOINT], gx[NUM_JOINT], gy[NUM_JOINT], gz[NUM_JOINT];
        float px[NUM_JOINT], py[NUM_JOINT], pz[NUM_JOINT];
        float* row = &s[buf][t * (NUM_JOINT * 4)];   // 76-float stride: LDS.128 conflict-free

        #pragma unroll
        for (int j = 0; j < NUM_JOINT; j++) {
            const float4 q = *(const float4*)&row[j * 4];
            float aw, ax, ay, az;
            if (j == 0) {
                aw = q.x; ax = q.y; ay = q.z; az = q.w;
            } else {
                const int p = parents[j];
                const float bw = q.x, bx = q.y, by = q.z, bz = q.w;
                aw = gw[p]*bw - gx[p]*bx - gy[p]*by - gz[p]*bz;
                ax = gw[p]*bx + gx[p]*bw + gy[p]*bz - gz[p]*by;
                ay = gw[p]*by - gx[p]*bz + gy[p]*bw + gz[p]*bx;
                az = gw[p]*bz + gx[p]*by - gy[p]*bx + gz[p]*bw;
            }
            gw[j] = aw; gx[j] = ax; gy[j] = ay; gz[j] = az;

            const float tx = c_off[j * 16 + 3];
            const float ty = c_off[j * 16 + 7];
            const float tz = c_off[j * 16 + 11];

            const float n  = aw*aw + ax*ax + ay*ay + az*az;
            const float sc = __fdividef(2.0f, n);

            const float cx = ay*tz - az*ty;
            const float cy = az*tx - ax*tz;
            const float cz = ax*ty - ay*tx;

            const float dx = aw*cx + (ay*cz - az*cy);
            const float dy = aw*cy + (az*cx - ax*cz);
            const float dz = aw*cz + (ax*cy - ay*cx);

            float ox = tx + sc * dx;
            float oy = ty + sc * dy;
            float oz = tz + sc * dz;
            if (j > 0) {
                const int p = parents[j];
                ox += px[p]; oy += py[p]; oz += pz[p];
            }
            px[j] = ox; py[j] = oy; pz[j] = oz;

            float4 o;
            o.x = ox + rx; o.y = oy + ry; o.z = oz + rz; o.w = 1.0f;
            *(float4*)&row[j * 4] = o;
        }
        __syncwarp();

        if (t == 0) {
            // Store tile i.
            asm volatile("fence.proxy.async.shared::cta;" ::: "memory");
            float* gdst = out + (tile0 + i) * TILE_FLOATS;
            asm volatile("cp.async.bulk.global.shared::cta.bulk_group [%0], [%1], %2;"
                         :: "l"(gdst), "r"(s0 + buf * TILE_BYTES),
                            "r"((uint32_t)TILE_BYTES) : "memory");
            asm volatile("cp.async.bulk.commit_group;" ::: "memory");

            // Prefetch tile i+2 into ring slot (i+2)%3. Safe once store of the
            // tile that previously occupied that slot (tile i-1) has drained:
            // wait_group 1 leaves only the just-committed store i outstanding.
            if (i + 2 < NTILE) {
                asm volatile("cp.async.bulk.wait_group 1;" ::: "memory");
                const int nb = (i + 2) % 3;
                tma_load(s0 + nb * TILE_BYTES, gbase + (i + 2) * TILE_FLOATS, m0 + nb * 8);
            }
        }
    }

    // Keep smem alive until the last stores drain.
    if (t == 0)
        asm volatile("cp.async.bulk.wait_group 0;" ::: "memory");
}

extern "C" void kernel_launch(void* const* d_in, const int* in_sizes, int n_in,
                              void* d_out, int out_size)
{
    const float* root    = (const float*)d_in[0];   // (B, 3)
    const float* joint   = (const float*)d_in[1];   // (B, 76)
    const float* offsets = (const float*)d_in[2];   // (19, 4, 4)
    float* out = (float*)d_out;                     // (B, 19, 4)

    cudaMemcpyToSymbolAsync(c_off, offsets, NUM_JOINT * 16 * sizeof(float),
                            0, cudaMemcpyDeviceToDevice, 0);

    const int B = in_sizes[1] / (NUM_JOINT * 4);
    const int tiles = B / BLOCK;                    // 8192
    const int grid = tiles / NTILE;                 // 2048
    fk_kernel<<<grid, BLOCK>>>(root, joint, out);
}

// round 7
// speedup vs baseline: 1.0481x; 1.0481x over previous
#include <cuda_runtime.h>
#include <cstdint>

#define NUM_JOINT 19
#define ROOT_SCALE 200.0f
#define WARPS 4
#define BLOCK (WARPS * 32)
#define TILE_FLOATS (32 * NUM_JOINT * 4)      // 2432 floats per warp-tile
#define TILE_BYTES  (TILE_FLOATS * 4)         // 9728 B

__constant__ float c_off[NUM_JOINT * 16];

__global__ __launch_bounds__(BLOCK, 5)
void fk_kernel(const float* __restrict__ root,
               const float* __restrict__ joint,
               float* __restrict__ out)
{
    __shared__ alignas(16) float s[WARPS][TILE_FLOATS];    // 38912 B
    __shared__ alignas(8)  unsigned long long mbar[WARPS];

    const int t    = threadIdx.x;
    const int w    = t >> 5;
    const int lane = t & 31;
    const uint32_t sw_addr = (uint32_t)__cvta_generic_to_shared(&s[w][0]);
    const uint32_t mw_addr = (uint32_t)__cvta_generic_to_shared(&mbar[w]);

    if (t < WARPS)
        asm volatile("mbarrier.init.shared.b64 [%0], 1;"
                     :: "r"((uint32_t)__cvta_generic_to_shared(&mbar[t])) : "memory");
    __syncthreads();   // mbars visible to all warps before any TMA targets them

    // Each warp owns tile (blockIdx.x*WARPS + w): independent load/compute/store.
    const long long tile = (long long)blockIdx.x * WARPS + w;
    const float* gsrc = joint + tile * TILE_FLOATS;

    if (lane == 0) {
        asm volatile("mbarrier.arrive.expect_tx.shared.b64 _, [%0], %1;"
                     :: "r"(mw_addr), "r"((uint32_t)TILE_BYTES) : "memory");
        asm volatile("cp.async.bulk.shared::cta.global.mbarrier::complete_tx::bytes "
                     "[%0], [%1], %2, [%3];"
                     :: "r"(sw_addr), "l"(gsrc), "r"((uint32_t)TILE_BYTES), "r"(mw_addr)
                     : "memory");
    }

    // Root fetch overlaps the TMA flight.
    const long long b = tile * 32 + lane;
    const float rx = __ldg(&root[b * 3 + 0]) * ROOT_SCALE;
    const float ry = __ldg(&root[b * 3 + 1]) * ROOT_SCALE;
    const float rz = __ldg(&root[b * 3 + 2]) * ROOT_SCALE;

    // Wait own tile (single use, parity 0).
    asm volatile(
        "{\n\t.reg .pred P;\n\t"
        "W%=:\n\t"
        "mbarrier.try_wait.parity.acquire.cta.shared::cta.b64 P, [%0], 0;\n\t"
        "@!P bra W%=;\n\t}"
        :: "r"(mw_addr) : "memory");

    // ---- FK via composite (non-unit) quaternions; LDS prefetched 1 joint ahead ----
    float gw[NUM_JOINT], gx[NUM_JOINT], gy[NUM_JOINT], gz[NUM_JOINT];
    float px[NUM_JOINT], py[NUM_JOINT], pz[NUM_JOINT];
    const int parents[NUM_JOINT] = {-1,0,1,2,3,2,5,6,7,2,9,10,11,0,13,14,0,16,17};
    float* row = &s[w][lane * (NUM_JOINT * 4)];   // 76-float stride: LDS.128 conflict-free

    float4 qn = *(const float4*)&row[0];
    #pragma unroll
    for (int j = 0; j < NUM_JOINT; j++) {
        const float4 q = qn;
        if (j + 1 < NUM_JOINT) qn = *(const float4*)&row[(j + 1) * 4];

        float aw, ax, ay, az;
        if (j == 0) {
            aw = q.x; ax = q.y; ay = q.z; az = q.w;
        } else {
            const int p = parents[j];
            const float bw = q.x, bx = q.y, by = q.z, bz = q.w;
            aw = gw[p]*bw - gx[p]*bx - gy[p]*by - gz[p]*bz;
            ax = gw[p]*bx + gx[p]*bw + gy[p]*bz - gz[p]*by;
            ay = gw[p]*by - gx[p]*bz + gy[p]*bw + gz[p]*bx;
            az = gw[p]*bz + gx[p]*by - gy[p]*bx + gz[p]*bw;
        }
        gw[j] = aw; gx[j] = ax; gy[j] = ay; gz[j] = az;

        // o = t + (2/|g|^2)*(aw*c + g x c),  c = g x t  (t from constant bank)
        const float tx = c_off[j * 16 + 3];
        const float ty = c_off[j * 16 + 7];
        const float tz = c_off[j * 16 + 11];

        const float n  = aw*aw + ax*ax + ay*ay + az*az;
        const float sc = __fdividef(2.0f, n);

        const float cx = ay*tz - az*ty;
        const float cy = az*tx - ax*tz;
        const float cz = ax*ty - ay*tx;

        const float dx = aw*cx + (ay*cz - az*cy);
        const float dy = aw*cy + (az*cx - ax*cz);
        const float dz = aw*cz + (ax*cy - ay*cx);

        float ox = tx + sc * dx;
        float oy = ty + sc * dy;
        float oz = tz + sc * dz;
        if (j > 0) {
            const int p = parents[j];
            ox += px[p]; oy += py[p]; oz += pz[p];
        }
        px[j] = ox; py[j] = oy; pz[j] = oz;

        float4 o;
        o.x = ox + rx; o.y = oy + ry; o.z = oz + rz; o.w = 1.0f;
        *(float4*)&row[j * 4] = o;
    }
    __syncwarp();

    // Per-warp bulk store of its own tile.
    if (lane == 0) {
        asm volatile("fence.proxy.async.shared::cta;" ::: "memory");
        float* gdst = out + tile * TILE_FLOATS;
        asm volatile("cp.async.bulk.global.shared::cta.bulk_group [%0], [%1], %2;"
                     :: "l"(gdst), "r"(sw_addr), "r"((uint32_t)TILE_BYTES) : "memory");
        asm volatile("cp.async.bulk.commit_group;" ::: "memory");
        asm volatile("cp.async.bulk.wait_group 0;" ::: "memory");   // smem must outlive store
    }
}

extern "C" void kernel_launch(void* const* d_in, const int* in_sizes, int n_in,
                              void* d_out, int out_size)
{
    const float* root    = (const float*)d_in[0];   // (B, 3)
    const float* joint   = (const float*)d_in[1];   // (B, 76)
    const float* offsets = (const float*)d_in[2];   // (19, 4, 4)
    float* out = (float*)d_out;                     // (B, 19, 4)

    cudaMemcpyToSymbolAsync(c_off, offsets, NUM_JOINT * 16 * sizeof(float),
                            0, cudaMemcpyDeviceToDevice, 0);

    const int B = in_sizes[1] / (NUM_JOINT * 4);    // 262144
    const int tiles = B / 32;                       // 8192 warp-tiles
    const int grid = tiles / WARPS;                 // 2048 CTAs
    fk_kernel<<<grid, BLOCK>>>(root, joint, out);
}

// round 8
// speedup vs baseline: 1.0614x; 1.0127x over previous
#include <cuda_runtime.h>
#include <cstdint>

#define NUM_JOINT 19
#define ROOT_SCALE 200.0f
#define BLOCK 32
#define TILE_FLOATS (BLOCK * NUM_JOINT * 4)   // 2432
#define TILE_BYTES  (TILE_FLOATS * 4)         // 9728

__constant__ float c_off[NUM_JOINT * 16];

__global__ __launch_bounds__(BLOCK, 24)
void fk_kernel(const float* __restrict__ root,
               const float* __restrict__ joint,
               float* __restrict__ out)
{
    __shared__ alignas(16) float s[TILE_FLOATS];
    __shared__ alignas(8) unsigned long long mbar;

    const int t = threadIdx.x;
    const uint32_t s_addr    = (uint32_t)__cvta_generic_to_shared(s);
    const uint32_t mbar_addr = (uint32_t)__cvta_generic_to_shared(&mbar);

    if (t == 0)
        asm volatile("mbarrier.init.shared.b64 [%0], 1;" :: "r"(mbar_addr) : "memory");
    __syncwarp();

    // One bulk async copy stages the whole CTA tile (gmem -> smem, same layout).
    const float* gsrc = joint + (size_t)blockIdx.x * TILE_FLOATS;
    if (t == 0) {
        asm volatile("mbarrier.arrive.expect_tx.shared.b64 _, [%0], %1;"
                     :: "r"(mbar_addr), "r"((uint32_t)TILE_BYTES) : "memory");
        asm volatile("cp.async.bulk.shared::cta.global.mbarrier::complete_tx::bytes "
                     "[%0], [%1], %2, [%3];"
                     :: "r"(s_addr), "l"(gsrc), "r"((uint32_t)TILE_BYTES), "r"(mbar_addr)
                     : "memory");
    }

    // Overlap the bulk load with the root fetch.
    const int b = blockIdx.x * BLOCK + t;
    const float rx = __ldg(&root[b * 3 + 0]) * ROOT_SCALE;
    const float ry = __ldg(&root[b * 3 + 1]) * ROOT_SCALE;
    const float rz = __ldg(&root[b * 3 + 2]) * ROOT_SCALE;

    // Wait for tile (phase parity 0).
    asm volatile(
        "{\n\t.reg .pred P;\n\t"
        "W%=:\n\t"
        "mbarrier.try_wait.parity.acquire.cta.shared::cta.b64 P, [%0], 0;\n\t"
        "@!P bra W%=;\n\t}"
        :: "r"(mbar_addr) : "memory");

    // Composite (non-unit) quaternion chain: R(g_p (x) q_j) = R(g_p) R(q_j).
    float gw[NUM_JOINT], gx[NUM_JOINT], gy[NUM_JOINT], gz[NUM_JOINT];
    float px[NUM_JOINT], py[NUM_JOINT], pz[NUM_JOINT];
    const int parents[NUM_JOINT] = {-1,0,1,2,3,2,5,6,7,2,9,10,11,0,13,14,0,16,17};
    float* row = &s[t * (NUM_JOINT * 4)];   // 76-float stride: LDS.128 conflict-free

    #pragma unroll
    for (int j = 0; j < NUM_JOINT; j++) {
        const float4 q = *(const float4*)&row[j * 4];
        float aw, ax, ay, az;
        if (j == 0) {
            aw = q.x; ax = q.y; ay = q.z; az = q.w;
        } else {
            const int p = parents[j];
            const float bw = q.x, bx = q.y, by = q.z, bz = q.w;
            aw = gw[p]*bw - gx[p]*bx - gy[p]*by - gz[p]*bz;
            ax = gw[p]*bx + gx[p]*bw + gy[p]*bz - gz[p]*by;
            ay = gw[p]*by - gx[p]*bz + gy[p]*bw + gz[p]*bx;
            az = gw[p]*bz + gx[p]*by - gy[p]*bx + gz[p]*bw;
        }
        gw[j] = aw; gx[j] = ax; gy[j] = ay; gz[j] = az;

        // o = t + (2/|g|^2) * (aw*c + g x c),  c = g x t   (t from constant bank)
        const float tx = c_off[j * 16 + 3];
        const float ty = c_off[j * 16 + 7];
        const float tz = c_off[j * 16 + 11];

        const float n  = aw*aw + ax*ax + ay*ay + az*az;
        const float sc = __fdividef(2.0f, n);

        const float cx = ay*tz - az*ty;
        const float cy = az*tx - ax*tz;
        const float cz = ax*ty - ay*tx;

        const float dx = aw*cx + (ay*cz - az*cy);
        const float dy = aw*cy + (az*cx - ax*cz);
        const float dz = aw*cz + (ax*cy - ay*cx);

        float ox = tx + sc * dx;
        float oy = ty + sc * dy;
        float oz = tz + sc * dz;
        if (j > 0) {
            const int p = parents[j];
            ox += px[p]; oy += py[p]; oz += pz[p];
        }
        px[j] = ox; py[j] = oy; pz[j] = oz;

        // In-place: position j (xyz + scaled root, w=1) overwrites quat j.
        float4 o;
        o.x = ox + rx; o.y = oy + ry; o.z = oz + rz; o.w = 1.0f;
        *(float4*)&row[j * 4] = o;
    }
    __syncwarp();

    // One bulk async store for the whole tile (smem -> gmem, same layout).
    if (t == 0) {
        asm volatile("fence.proxy.async.shared::cta;" ::: "memory");
        float* gdst = out + (size_t)blockIdx.x * TILE_FLOATS;
        asm volatile("cp.async.bulk.global.shared::cta.bulk_group [%0], [%1], %2;"
                     :: "l"(gdst), "r"(s_addr), "r"((uint32_t)TILE_BYTES) : "memory");
        asm volatile("cp.async.bulk.commit_group;" ::: "memory");
        asm volatile("cp.async.bulk.wait_group 0;" ::: "memory");  // smem must outlive store
    }
}

extern "C" void kernel_launch(void* const* d_in, const int* in_sizes, int n_in,
                              void* d_out, int out_size)
{
    const float* root    = (const float*)d_in[0];   // (B, 3)
    const float* joint   = (const float*)d_in[1];   // (B, 76)
    const float* offsets = (const float*)d_in[2];   // (19, 4, 4)
    float* out = (float*)d_out;                     // (B, 19, 4)

    cudaMemcpyToSymbolAsync(c_off, offsets, NUM_JOINT * 16 * sizeof(float),
                            0, cudaMemcpyDeviceToDevice, 0);

    const int B = in_sizes[1] / (NUM_JOINT * 4);
    const int grid = B / BLOCK;                     // 8192
    fk_kernel<<<grid, BLOCK>>>(root, joint, out);
}

// round 9
// speedup vs baseline: 1.0740x; 1.0118x over previous
#include <cuda_runtime.h>
#include <cstdint>

#define NUM_JOINT 19
#define ROOT_SCALE 200.0f
#define BLOCK 32
#define TILE_FLOATS (BLOCK * NUM_JOINT * 4)   // 2432
#define TILE_BYTES  (TILE_FLOATS * 4)         // 9728
#define GRID 1628                              // 148 SMs * 11 CTAs

__constant__ float c_off[NUM_JOINT * 16];

__device__ __forceinline__ void tma_load(uint32_t sdst, const float* gsrc, uint32_t mb) {
    asm volatile("mbarrier.arrive.expect_tx.shared.b64 _, [%0], %1;"
                 :: "r"(mb), "r"((uint32_t)TILE_BYTES) : "memory");
    asm volatile("cp.async.bulk.shared::cta.global.mbarrier::complete_tx::bytes "
                 "[%0], [%1], %2, [%3];"
                 :: "r"(sdst), "l"(gsrc), "r"((uint32_t)TILE_BYTES), "r"(mb) : "memory");
}

__global__ __launch_bounds__(BLOCK, 11)
void fk_kernel(const float* __restrict__ root,
               const float* __restrict__ joint,
               float* __restrict__ out,
               int ntiles)
{
    __shared__ alignas(16) float s[2][TILE_FLOATS];        // 19456 B
    __shared__ alignas(8)  unsigned long long mbar[2];

    const int t = threadIdx.x;
    const uint32_t s0 = (uint32_t)__cvta_generic_to_shared(&s[0][0]);
    const uint32_t m0 = (uint32_t)__cvta_generic_to_shared(&mbar[0]);

    if (t == 0) {
        asm volatile("mbarrier.init.shared.b64 [%0], 1;" :: "r"(m0)     : "memory");
        asm volatile("mbarrier.init.shared.b64 [%0], 1;" :: "r"(m0 + 8) : "memory");
    }
    __syncwarp();

    const int parents[NUM_JOINT] = {-1,0,1,2,3,2,5,6,7,2,9,10,11,0,13,14,0,16,17};

    // Prologue: load first tile into buf 0.
    if (t == 0 && blockIdx.x < ntiles)
        tma_load(s0, joint + (size_t)blockIdx.x * TILE_FLOATS, m0);

    int it = 0;
    for (int tile = blockIdx.x; tile < ntiles; tile += GRID, it++) {
        const int buf = it & 1;
        const uint32_t parity = (uint32_t)((it >> 1) & 1);
        const uint32_t sbuf = s0 + buf * TILE_BYTES;
        const uint32_t mb   = m0 + buf * 8;

        // Root fetch overlaps the load-wait window.
        const long long b = (long long)tile * BLOCK + t;
        const float rx = __ldg(&root[b * 3 + 0]) * ROOT_SCALE;
        const float ry = __ldg(&root[b * 3 + 1]) * ROOT_SCALE;
        const float rz = __ldg(&root[b * 3 + 2]) * ROOT_SCALE;

        // Wait for this tile's data (HW-sleep wait, not spin).
        asm volatile(
            "{\n\t.reg .pred P;\n\t"
            "W%=:\n\t"
            "mbarrier.try_wait.parity.acquire.cta.shared::cta.b64 P, [%0], %1, 0x989680;\n\t"
            "@!P bra W%=;\n\t}"
            :: "r"(mb), "r"(parity) : "memory");

        // Prefetch next tile into the other buffer. Its previous store (tile-GRID,
        // committed one iteration ago) must be drained first: wait_group 0.
        if (t == 0 && tile + GRID < ntiles) {
            asm volatile("cp.async.bulk.wait_group 0;" ::: "memory");
            tma_load(s0 + (buf ^ 1) * TILE_BYTES,
                     joint + (size_t)(tile + GRID) * TILE_FLOATS,
                     m0 + (buf ^ 1) * 8);
        }

        // ---- FK chain via composite (non-unit) quaternions, in-place in s[buf] ----
        float gw[NUM_JOINT], gx[NUM_JOINT], gy[NUM_JOINT], gz[NUM_JOINT];
        float px[NUM_JOINT], py[NUM_JOINT], pz[NUM_JOINT];
        float* row = &s[buf][t * (NUM_JOINT * 4)];   // 76-float stride: conflict-free

        #pragma unroll
        for (int j = 0; j < NUM_JOINT; j++) {
            const float4 q = *(const float4*)&row[j * 4];
            float aw, ax, ay, az;
            if (j == 0) {
                aw = q.x; ax = q.y; ay = q.z; az = q.w;
            } else {
                const int p = parents[j];
                const float bw = q.x, bx = q.y, by = q.z, bz = q.w;
                aw = gw[p]*bw - gx[p]*bx - gy[p]*by - gz[p]*bz;
                ax = gw[p]*bx + gx[p]*bw + gy[p]*bz - gz[p]*by;
                ay = gw[p]*by - gx[p]*bz + gy[p]*bw + gz[p]*bx;
                az = gw[p]*bz + gx[p]*by - gy[p]*bx + gz[p]*bw;
            }
            gw[j] = aw; gx[j] = ax; gy[j] = ay; gz[j] = az;

            const float tx = c_off[j * 16 + 3];
            const float ty = c_off[j * 16 + 7];
            const float tz = c_off[j * 16 + 11];

            const float n  = aw*aw + ax*ax + ay*ay + az*az;
            const float sc = __fdividef(2.0f, n);

            const float cx = ay*tz - az*ty;
            const float cy = az*tx - ax*tz;
            const float cz = ax*ty - ay*tx;

            const float dx = aw*cx + (ay*cz - az*cy);
            const float dy = aw*cy + (az*cx - ax*cz);
            const float dz = aw*cz + (ax*cy - ay*cx);

            float ox = tx + sc * dx;
            float oy = ty + sc * dy;
            float oz = tz + sc * dz;
            if (j > 0) {
                const int p = parents[j];
                ox += px[p]; oy += py[p]; oz += pz[p];
            }
            px[j] = ox; py[j] = oy; pz[j] = oz;

            float4 o;
            o.x = ox + rx; o.y = oy + ry; o.z = oz + rz; o.w = 1.0f;
            *(float4*)&row[j * 4] = o;
        }
        __syncwarp();

        // Commit bulk store of this tile; it drains during the next compute phase.
        if (t == 0) {
            asm volatile("fence.proxy.async.shared::cta;" ::: "memory");
            float* gdst = out + (size_t)tile * TILE_FLOATS;
            asm volatile("cp.async.bulk.global.shared::cta.bulk_group [%0], [%1], %2;"
                         :: "l"(gdst), "r"(sbuf), "r"((uint32_t)TILE_BYTES) : "memory");
            asm volatile("cp.async.bulk.commit_group;" ::: "memory");
        }
    }

    // smem must outlive the final store.
    if (t == 0)
        asm volatile("cp.async.bulk.wait_group 0;" ::: "memory");
}

extern "C" void kernel_launch(void* const* d_in, const int* in_sizes, int n_in,
                              void* d_out, int out_size)
{
    const float* root    = (const float*)d_in[0];   // (B, 3)
    const float* joint   = (const float*)d_in[1];   // (B, 76)
    const float* offsets = (const float*)d_in[2];   // (19, 4, 4)
    float* out = (float*)d_out;                     // (B, 19, 4)

    cudaMemcpyToSymbolAsync(c_off, offsets, NUM_JOINT * 16 * sizeof(float),
                            0, cudaMemcpyDeviceToDevice, 0);

    const int B = in_sizes[1] / (NUM_JOINT * 4);    // 262144
    const int ntiles = B / BLOCK;                   // 8192
    fk_kernel<<<GRID, BLOCK>>>(root, joint, out, ntiles);
}